// round 8
// baseline (speedup 1.0000x reference)
#include <cuda_runtime.h>
#include <cuda_bf16.h>
#include <math.h>

#define NT 256

namespace {

constexpr int Bc  = 2;
constexpr int Hc  = 16;
constexpr int Sc  = 4096;
constexpr int DKc = 128;
constexpr int DVc = 256;
constexpr int Lc  = 64;     // chunk length
constexpr int DVB = 64;     // Dv block per CTA
constexpr int BHc = Bc * Hc;          // 32
constexpr int NCH = Sc / Lc;          // 64 chunks
constexpr int NBv = DVc / DVB;        // 4 Dv blocks

constexpr float kScale = 0.08838834764831845f;   // 128^-0.5
constexpr long long OUT_ELEMS   = (long long)BHc * Sc * DVc;     // 33554432
constexpr long long STATE_ELEMS = (long long)BHc * DKc * DVc;    // 1048576

typedef unsigned long long u64;

// Row swizzle for d-indexed rows (q/k/St): XOR bits [2:5) of the float column
// index by (row>>2)&7. Preserves 16B (LD4) alignment.
__device__ __host__ __forceinline__ int SWZ(int row, int d) {
  return d ^ (((row >> 2) & 7) << 2);
}

struct Smem {
  float q[Lc][DKc];      // normalized q chunk (row-swizzled)
  float k[Lc][DKc];      // normalized k chunk (row-swizzled)
  float v[Lc][DVB];      // v slice; becomes R = gexp*(V - K@S) in place
  float a[Lc][Lc];       // kk^T scratch half0 -> gated A (strict lower)
  float w[Lc][Lc];       // qk^T scratch half0 -> gated qkg (causal)
  float t[Lc][Lc];       // kk^T scratch half1 -> T = A^-1 diag(beta)
  float c[Lc][DVB];      // qk^T scratch half1 -> solve scratch P -> correction C
  float St[DVB][DKc];    // running state slice, TRANSPOSED (row-swizzled)
  float part[2][Lc][4];  // norm partial sums
  float ninv[2][Lc];
  float gcum[Lc];
  float gexp[Lc];
  float ginv[Lc];
  float beta[Lc];
};

#define LD4(dst, src) *reinterpret_cast<float4*>(dst) = *reinterpret_cast<const float4*>(src)

// ---- packed f32x2 helpers (Blackwell FFMA2 path, PTX-only) ----------------
__device__ __forceinline__ u64 pk2(float a) {
  u64 r; unsigned int ai = __float_as_uint(a);
  asm("mov.b64 %0, {%1, %1};" : "=l"(r) : "r"(ai));
  return r;
}
__device__ __forceinline__ u64 ffma2(u64 a, u64 b, u64 c) {
  u64 d;
  asm("fma.rn.f32x2 %0, %1, %2, %3;" : "=l"(d) : "l"(a), "l"(b), "l"(c));
  return d;
}
__device__ __forceinline__ float2 upk(u64 a) {
  unsigned int lo, hi;
  asm("mov.b64 {%0, %1}, %2;" : "=r"(lo), "=r"(hi) : "l"(a));
  return make_float2(__uint_as_float(lo), __uint_as_float(hi));
}
__device__ __forceinline__ float foldp(u64 a) {  // sum even/odd-d partials
  float2 f = upk(a);
  return f.x + f.y;
}
// load 16B (4 floats = 2 d-pairs) as two u64 lanes
__device__ __forceinline__ void ld2p(u64 p[2], const float* addr) {
  ulonglong2 t = *reinterpret_cast<const ulonglong2*>(addr);
  p[0] = t.x; p[1] = t.y;
}

// (broadcast-A form for phases E/F)
__device__ __forceinline__ void mm4x4p(u64 acc[4][2], const float Af[4][4],
                                       const u64 Bv[4][2]) {
  #pragma unroll
  for (int r = 0; r < 4; ++r)
    #pragma unroll
    for (int kk = 0; kk < 4; ++kk) {
      u64 pa = pk2(Af[r][kk]);
      acc[r][0] = ffma2(pa, Bv[kk][0], acc[r][0]);
      acc[r][1] = ffma2(pa, Bv[kk][1], acc[r][1]);
    }
}
__device__ __forceinline__ void ldBv(u64 Bv2[2], const float* p) {
  ulonglong2 b = *reinterpret_cast<const ulonglong2*>(p);
  Bv2[0] = b.x; Bv2[1] = b.y;
}

__global__ void __launch_bounds__(NT, 1) gdn_kernel(
    const float* __restrict__ gq, const float* __restrict__ gk,
    const float* __restrict__ gv, const float* __restrict__ gg,
    const float* __restrict__ gb, float* __restrict__ out,
    long long out_elems)
{
  extern __shared__ char smem_raw[];
  Smem& s = *reinterpret_cast<Smem*>(smem_raw);

  const int tid = threadIdx.x;
  const int vb  = blockIdx.x;   // Dv block
  const int bh  = blockIdx.y;   // fused batch*head

  const size_t qkbase = (size_t)bh * Sc * DKc;
  const size_t vbase  = (size_t)bh * Sc * DVc + (size_t)vb * DVB;
  const size_t gbase  = (size_t)bh * Sc;

  for (int i = tid; i < DKc * DVB; i += NT) (&s.St[0][0])[i] = 0.f;
  __syncthreads();

  const int ty = tid >> 4;            // 0..15
  const int tx = tid & 15;            // 0..15
  const int ldrow = (tid * 32) >> 7;  // q/k load row (0..63)
  const int ldcol = (tid * 32) & 127; // q/k load col offset

  // ---- Phase-B triangular tile assignment (computed once) -----------------
  // Lower-triangle 4x4 tiles of the 64x64 kk^T / qk^T matrices only.
  //  threads   0..15 : diagonal tiles (t,t), full d-range, single coverage
  //  threads  16..31 : strict tiles e=0..15, full d-range, single coverage
  //  threads  32..239: strict tiles e=16..119, HALF d-range each (pairs)
  //  threads 240..255: redundant compute (tile 119), stores disabled
  int bti, btj, bhoff;
  bool bfull, bstore, bsingle;
  {
    int t = tid;
    if (t < 16) {
      bti = t; btj = t; bhoff = 0; bfull = true; bstore = true; bsingle = true;
    } else {
      int e;
      if (t < 32) { e = t - 16; bhoff = 0; bfull = true; bstore = true; bsingle = true; }
      else {
        e = 16 + ((t - 32) >> 1);
        bhoff = ((t - 32) & 1) * 4;
        bfull = false; bsingle = false;
        bstore = (e <= 119);
        if (e > 119) e = 119;
      }
      int ti = 1;
      while ((ti + 1) * ti / 2 <= e) ++ti;
      bti = ti; btj = e - ti * (ti - 1) / 2;
    }
  }

  for (int n = 0; n < NCH; ++n) {
    // ================= Phase A: load + normalize q,k; load v,g,beta ========
    const float* qg = gq + qkbase + (size_t)n * Lc * DKc + tid * 32;
    const float* kg = gk + qkbase + (size_t)n * Lc * DKc + tid * 32;
    float4 bq[8], bk[8];
    float sq = 0.f, sk = 0.f;
    #pragma unroll
    for (int u = 0; u < 8; ++u) {
      float4 x = *reinterpret_cast<const float4*>(qg + u * 4);
      float4 y = *reinterpret_cast<const float4*>(kg + u * 4);
      bq[u] = x; bk[u] = y;
      sq += x.x * x.x + x.y * x.y + x.z * x.z + x.w * x.w;
      sk += y.x * y.x + y.y * y.y + y.z * y.z + y.w * y.w;
    }
    s.part[0][ldrow][ldcol >> 5] = sq;
    s.part[1][ldrow][ldcol >> 5] = sk;
    #pragma unroll
    for (int u = 0; u < 4; ++u) {
      int f = tid * 4 + u;
      int r = f >> 4, c4 = (f & 15) * 4;
      LD4(&s.v[r][c4], gv + vbase + (size_t)(n * Lc + r) * DVc + c4);
    }
    if (tid < Lc) {
      s.gcum[tid] = gg[gbase + n * Lc + tid];
      s.beta[tid] = gb[gbase + n * Lc + tid];
    }
    __syncthreads();

    if (tid < 2 * Lc) {
      int w = tid >> 6, r = tid & 63;
      float ssum = s.part[w][r][0] + s.part[w][r][1] + s.part[w][r][2] + s.part[w][r][3];
      s.ninv[w][r] = 1.f / (sqrtf(ssum) + 1e-6f);
    }
    if (tid == 128) {  // sequential cumsum over 64 gates (cheap)
      float acc = 0.f;
      for (int i = 0; i < Lc; ++i) { acc += s.gcum[i]; s.gcum[i] = acc; }
    }
    __syncthreads();

    if (tid < Lc) {
      float e = expf(s.gcum[tid]);
      s.gexp[tid] = e;
      s.ginv[tid] = 1.f / e;
    }
    {
      float iq = s.ninv[0][ldrow], ik = s.ninv[1][ldrow];
      const int swr = ((ldrow >> 2) & 7) << 2;
      #pragma unroll
      for (int u = 0; u < 8; ++u) {
        int cc = (ldcol + u * 4) ^ swr;   // 16B-aligned swizzled column
        float4 x = bq[u];
        x.x *= iq; x.y *= iq; x.z *= iq; x.w *= iq;
        *reinterpret_cast<float4*>(&s.q[ldrow][cc]) = x;
        float4 y = bk[u];
        y.x *= ik; y.y *= ik; y.z *= ik; y.w *= ik;
        *reinterpret_cast<float4*>(&s.k[ldrow][cc]) = y;
      }
    }
    __syncthreads();

    // ===== Phase B (triangular remap, split-K): raw kk^T and qk^T tiles ====
    // Output: raw partials to scratch (a/t for kk, w/c for qk); combined and
    // gated after the barrier below.
    {
      const int i0 = bti * 4, j0 = btj * 4;
      const int sA = (bti & 7) << 2, sB = (btj & 7) << 2;
      u64 aA[4][4] = {}, aQ[4][4] = {};
      if (bfull) {
        #pragma unroll 2
        for (int d = 0; d < DKc; d += 4) {
          u64 Bp[4][2];
          #pragma unroll
          for (int cc = 0; cc < 4; ++cc) ld2p(Bp[cc], &s.k[j0 + cc][d ^ sB]);
          #pragma unroll
          for (int r = 0; r < 4; ++r) {
            u64 Ap[2];
            ld2p(Ap, &s.k[i0 + r][d ^ sA]);
            #pragma unroll
            for (int cc = 0; cc < 4; ++cc) {
              aA[r][cc] = ffma2(Ap[0], Bp[cc][0], aA[r][cc]);
              aA[r][cc] = ffma2(Ap[1], Bp[cc][1], aA[r][cc]);
            }
            ld2p(Ap, &s.q[i0 + r][d ^ sA]);
            #pragma unroll
            for (int cc = 0; cc < 4; ++cc) {
              aQ[r][cc] = ffma2(Ap[0], Bp[cc][0], aQ[r][cc]);
              aQ[r][cc] = ffma2(Ap[1], Bp[cc][1], aQ[r][cc]);
            }
          }
        }
      } else {
        #pragma unroll 2
        for (int u = 0; u < 16; ++u) {
          const int d = u * 8 + bhoff;   // interleaved d-quads per half
          u64 Bp[4][2];
          #pragma unroll
          for (int cc = 0; cc < 4; ++cc) ld2p(Bp[cc], &s.k[j0 + cc][d ^ sB]);
          #pragma unroll
          for (int r = 0; r < 4; ++r) {
            u64 Ap[2];
            ld2p(Ap, &s.k[i0 + r][d ^ sA]);
            #pragma unroll
            for (int cc = 0; cc < 4; ++cc) {
              aA[r][cc] = ffma2(Ap[0], Bp[cc][0], aA[r][cc]);
              aA[r][cc] = ffma2(Ap[1], Bp[cc][1], aA[r][cc]);
            }
            ld2p(Ap, &s.q[i0 + r][d ^ sA]);
            #pragma unroll
            for (int cc = 0; cc < 4; ++cc) {
              aQ[r][cc] = ffma2(Ap[0], Bp[cc][0], aQ[r][cc]);
              aQ[r][cc] = ffma2(Ap[1], Bp[cc][1], aQ[r][cc]);
            }
          }
        }
      }
      if (bstore) {
        const bool h1 = (!bfull) && (bhoff != 0);
        #pragma unroll
        for (int r = 0; r < 4; ++r) {
          float4 fa = make_float4(foldp(aA[r][0]), foldp(aA[r][1]),
                                  foldp(aA[r][2]), foldp(aA[r][3]));
          float4 fq = make_float4(foldp(aQ[r][0]), foldp(aQ[r][1]),
                                  foldp(aQ[r][2]), foldp(aQ[r][3]));
          if (!h1) {
            *reinterpret_cast<float4*>(&s.a[i0 + r][j0]) = fa;
            *reinterpret_cast<float4*>(&s.w[i0 + r][j0]) = fq;
            if (bsingle) {  // no partner: zero the half1 scratch
              *reinterpret_cast<float4*>(&s.t[i0 + r][j0]) = make_float4(0,0,0,0);
              *reinterpret_cast<float4*>(&s.c[i0 + r][j0]) = make_float4(0,0,0,0);
            }
          } else {
            *reinterpret_cast<float4*>(&s.t[i0 + r][j0]) = fa;
            *reinterpret_cast<float4*>(&s.c[i0 + r][j0]) = fq;
          }
        }
      }
    }
    // no barrier yet: phase C touches only St/q/k/v.

    // ===== Phase C (fused, d-pair packed): R = gexp*(V - K@St^T) in s.v ;
    //       O_inter = Q@St^T folded into qI registers ========================
    float qI[4][4];   // persistent O_inter tile, consumed in F
    {
      const int r0 = ty * 4, c0 = tx * 4;
      const int sA = (ty & 7) << 2, sB = (tx & 7) << 2;
      u64 aK[4][4] = {}, aI[4][4] = {};
      #pragma unroll 2
      for (int d = 0; d < DKc; d += 4) {
        u64 Bp[4][2];
        #pragma unroll
        for (int cc = 0; cc < 4; ++cc) ld2p(Bp[cc], &s.St[c0 + cc][d ^ sB]);
        #pragma unroll
        for (int r = 0; r < 4; ++r) {
          u64 Ap[2];
          ld2p(Ap, &s.k[r0 + r][d ^ sA]);
          #pragma unroll
          for (int cc = 0; cc < 4; ++cc) {
            aK[r][cc] = ffma2(Ap[0], Bp[cc][0], aK[r][cc]);
            aK[r][cc] = ffma2(Ap[1], Bp[cc][1], aK[r][cc]);
          }
          ld2p(Ap, &s.q[r0 + r][d ^ sA]);
          #pragma unroll
          for (int cc = 0; cc < 4; ++cc) {
            aI[r][cc] = ffma2(Ap[0], Bp[cc][0], aI[r][cc]);
            aI[r][cc] = ffma2(Ap[1], Bp[cc][1], aI[r][cc]);
          }
        }
      }
      #pragma unroll
      for (int r = 0; r < 4; ++r) {
        float ge = s.gexp[r0 + r];
        float4 vv = *reinterpret_cast<float4*>(&s.v[r0 + r][c0]);
        vv.x = ge * (vv.x - foldp(aK[r][0]));
        vv.y = ge * (vv.y - foldp(aK[r][1]));
        vv.z = ge * (vv.z - foldp(aK[r][2]));
        vv.w = ge * (vv.w - foldp(aK[r][3]));
        *reinterpret_cast<float4*>(&s.v[r0 + r][c0]) = vv;
        #pragma unroll
        for (int cc = 0; cc < 4; ++cc) qI[r][cc] = foldp(aI[r][cc]);
      }
    }
    __syncthreads();   // scratch tiles complete, s.v(R) complete

    // ===== Phase B2: combine halves, gate + mask in place ==================
    // s.a = strict_lower( beta_i*ginv_i * (a+t) * gexp_j )
    // s.w = causal( (w+c) * gexp_j * ginv_i )
    {
      const int ci  = tid >> 2;          // row
      const int cj0 = (tid & 3) * 16;    // 16-wide column span
      const float bi = s.beta[ci] * s.ginv[ci];
      const float gi = s.ginv[ci];
      #pragma unroll
      for (int u = 0; u < 16; u += 4) {
        const int j = cj0 + u;
        float4 a0 = *reinterpret_cast<const float4*>(&s.a[ci][j]);
        float4 a1 = *reinterpret_cast<const float4*>(&s.t[ci][j]);
        float4 q0 = *reinterpret_cast<const float4*>(&s.w[ci][j]);
        float4 q1 = *reinterpret_cast<const float4*>(&s.c[ci][j]);
        float4 ra, rw;
        ra.x = (j + 0 < ci) ? bi * (a0.x + a1.x) * s.gexp[j + 0] : 0.f;
        ra.y = (j + 1 < ci) ? bi * (a0.y + a1.y) * s.gexp[j + 1] : 0.f;
        ra.z = (j + 2 < ci) ? bi * (a0.z + a1.z) * s.gexp[j + 2] : 0.f;
        ra.w = (j + 3 < ci) ? bi * (a0.w + a1.w) * s.gexp[j + 3] : 0.f;
        rw.x = (j + 0 <= ci) ? (q0.x + q1.x) * s.gexp[j + 0] * gi : 0.f;
        rw.y = (j + 1 <= ci) ? (q0.y + q1.y) * s.gexp[j + 1] * gi : 0.f;
        rw.z = (j + 2 <= ci) ? (q0.z + q1.z) * s.gexp[j + 2] * gi : 0.f;
        rw.w = (j + 3 <= ci) ? (q0.w + q1.w) * s.gexp[j + 3] * gi : 0.f;
        *reinterpret_cast<float4*>(&s.a[ci][j]) = ra;
        *reinterpret_cast<float4*>(&s.w[ci][j]) = rw;
      }
    }
    __syncthreads();

    // ===== Phase D: blocked forward substitution, T = A^-1 diag(beta) ======
    if (tid < Lc) {
      float tc[32];
      #pragma unroll
      for (int i = 0; i < 32; ++i) {
        float v0 = (tid == i) ? s.beta[i] : 0.f;
        float v1 = 0.f, v2 = 0.f, v3 = 0.f;
        int j = 0;
        #pragma unroll
        for (; j + 4 <= i; j += 4) {
          v0 -= s.a[i][j + 0] * tc[j + 0];
          v1 -= s.a[i][j + 1] * tc[j + 1];
          v2 -= s.a[i][j + 2] * tc[j + 2];
          v3 -= s.a[i][j + 3] * tc[j + 3];
        }
        #pragma unroll
        for (; j < i; ++j) v0 -= s.a[i][j] * tc[j];
        float val = (v0 + v1) + (v2 + v3);
        tc[i] = val;
        s.t[i][tid] = val;
      }
    }
    __syncthreads();
    // Off-diagonal: P[32][64] = A[32:64][0:32] @ T[0:32][:]  (all 256 threads)
    {
      const int rp0 = (tid >> 5) * 4;   // 0..28
      const int cp0 = (tid & 31) * 2;   // 0..62
      float accP[4][2] = {};
      #pragma unroll
      for (int j = 0; j < 32; j += 4) {
        float Bf[4][2];
        #pragma unroll
        for (int jj = 0; jj < 4; ++jj) {
          float2 t2 = *reinterpret_cast<const float2*>(&s.t[j + jj][cp0]);
          Bf[jj][0] = t2.x; Bf[jj][1] = t2.y;
        }
        #pragma unroll
        for (int r = 0; r < 4; ++r) {
          float4 av = *reinterpret_cast<const float4*>(&s.a[32 + rp0 + r][j]);
          accP[r][0] += av.x * Bf[0][0] + av.y * Bf[1][0] + av.z * Bf[2][0] + av.w * Bf[3][0];
          accP[r][1] += av.x * Bf[0][1] + av.y * Bf[1][1] + av.z * Bf[2][1] + av.w * Bf[3][1];
        }
      }
      #pragma unroll
      for (int r = 0; r < 4; ++r) {
        s.c[rp0 + r][cp0]     = accP[r][0];
        s.c[rp0 + r][cp0 + 1] = accP[r][1];
      }
    }
    __syncthreads();
    // Block 1: rows 32..63 (4-accumulator ILP)
    if (tid < Lc) {
      float tc[32];
      #pragma unroll
      for (int i = 0; i < 32; ++i) {
        int gi = 32 + i;
        float v0 = ((tid == gi) ? s.beta[gi] : 0.f) - s.c[i][tid];
        float v1 = 0.f, v2 = 0.f, v3 = 0.f;
        int j = 0;
        #pragma unroll
        for (; j + 4 <= i; j += 4) {
          v0 -= s.a[gi][32 + j + 0] * tc[j + 0];
          v1 -= s.a[gi][32 + j + 1] * tc[j + 1];
          v2 -= s.a[gi][32 + j + 2] * tc[j + 2];
          v3 -= s.a[gi][32 + j + 3] * tc[j + 3];
        }
        #pragma unroll
        for (; j < i; ++j) v0 -= s.a[gi][32 + j] * tc[j];
        float val = (v0 + v1) + (v2 + v3);
        tc[i] = val;
        s.t[gi][tid] = val;
      }
    }
    __syncthreads();

    // ===== Phase E: C = T @ R  (triangular: T[i][j]=0 for j>i) =============
    {
      const int i0 = ty * 4, c0 = tx * 4;
      u64 aC[4][2] = {};
      #pragma unroll 2
      for (int j = 0; j <= i0; j += 4) {   // last block covers j=i0..i0+3
        u64 Bv[4][2];
        #pragma unroll
        for (int jj = 0; jj < 4; ++jj) ldBv(Bv[jj], &s.v[j + jj][c0]);
        float Af[4][4];
        #pragma unroll
        for (int r = 0; r < 4; ++r) LD4(&Af[r][0], &s.t[i0 + r][j]);
        mm4x4p(aC, Af, Bv);
      }
      #pragma unroll
      for (int r = 0; r < 4; ++r) {
        float2 f0 = upk(aC[r][0]), f1 = upk(aC[r][1]);
        *reinterpret_cast<float4*>(&s.c[i0 + r][c0]) =
            make_float4(f0.x, f0.y, f1.x, f1.y);
      }
    }
    __syncthreads();

    // ===== Phase F: O = kScale*(gexp_i * qI + qkg @ C), store to gmem ======
    {
      const int i0 = ty * 4, c0 = tx * 4;
      u64 aO[4][2] = {};
      #pragma unroll 2
      for (int j = 0; j <= i0; j += 4) {
        u64 Bv[4][2];
        #pragma unroll
        for (int jj = 0; jj < 4; ++jj) ldBv(Bv[jj], &s.c[j + jj][c0]);
        float Af[4][4];
        #pragma unroll
        for (int r = 0; r < 4; ++r) LD4(&Af[r][0], &s.w[i0 + r][j]);
        mm4x4p(aO, Af, Bv);
      }
      const size_t obase = ((size_t)bh * Sc + (size_t)n * Lc) * DVc + (size_t)vb * DVB;
      #pragma unroll
      for (int r = 0; r < 4; ++r) {
        int i = i0 + r;
        float ge = s.gexp[i];
        float2 o0 = upk(aO[r][0]), o1 = upk(aO[r][1]);
        float4 o;
        o.x = kScale * (ge * qI[r][0] + o0.x);
        o.y = kScale * (ge * qI[r][1] + o0.y);
        o.z = kScale * (ge * qI[r][2] + o1.x);
        o.w = kScale * (ge * qI[r][3] + o1.y);
        *reinterpret_cast<float4*>(&out[obase + (size_t)i * DVc + c0]) = o;
      }
    }

    // ===== Phase G: St[c][d] = egt*St[c][d] + sum_i (gexp_i C[i][c]) k[i][d]
    {
      const int c0 = (tid & 15) * 4;
      const int d0 = (tid >> 4) * 8;
      const int sc = ((tid & 15) & 7) << 2;  // swizzle for St rows c0..c0+3
      const float egt = s.gexp[Lc - 1];
      const u64 egt2 = pk2(egt);
      u64 acc[4][4] = {};
      #pragma unroll 2
      for (int i = 0; i < Lc; ++i) {
        const int si = ((i >> 2) & 7) << 2;
        u64 kp[4];
        ld2p(kp,     &s.k[i][d0 ^ si]);
        ld2p(kp + 2, &s.k[i][(d0 + 4) ^ si]);
        float4 cv = *reinterpret_cast<const float4*>(&s.c[i][c0]);
        float ge = s.gexp[i];
        u64 gc0 = pk2(ge * cv.x), gc1 = pk2(ge * cv.y);
        u64 gc2 = pk2(ge * cv.z), gc3 = pk2(ge * cv.w);
        #pragma unroll
        for (int dp = 0; dp < 4; ++dp) {
          acc[0][dp] = ffma2(gc0, kp[dp], acc[0][dp]);
          acc[1][dp] = ffma2(gc1, kp[dp], acc[1][dp]);
          acc[2][dp] = ffma2(gc2, kp[dp], acc[2][dp]);
          acc[3][dp] = ffma2(gc3, kp[dp], acc[3][dp]);
        }
      }
      #pragma unroll
      for (int cc = 0; cc < 4; ++cc) {
        float* row = &s.St[c0 + cc][0];
        u64* p0 = reinterpret_cast<u64*>(row + (d0 ^ sc));
        u64* p1 = reinterpret_cast<u64*>(row + ((d0 + 4) ^ sc));
        p0[0] = ffma2(p0[0], egt2, acc[cc][0]);
        p0[1] = ffma2(p0[1], egt2, acc[cc][1]);
        p1[0] = ffma2(p1[0], egt2, acc[cc][2]);
        p1[1] = ffma2(p1[1], egt2, acc[cc][3]);
      }
    }
    __syncthreads();
  }  // chunk loop

  // Final state (second tuple element), if the output buffer includes it.
  if (out_elems >= OUT_ELEMS + STATE_ELEMS) {
    float* st = out + OUT_ELEMS + (size_t)bh * DKc * DVc + (size_t)vb * DVB;
    for (int f = tid; f < DKc * DVB; f += NT) {
      int d = f >> 6;        // 0..127
      int c = f & 63;        // 0..63 (contiguous for coalescing)
      st[(size_t)d * DVc + c] = s.St[c][SWZ(c, d)];
    }
  }
}

}  // namespace

extern "C" void kernel_launch(void* const* d_in, const int* in_sizes, int n_in,
                              void* d_out, int out_size) {
  (void)in_sizes; (void)n_in;
  const float* q  = (const float*)d_in[0];
  const float* k  = (const float*)d_in[1];
  const float* v  = (const float*)d_in[2];
  const float* g  = (const float*)d_in[3];
  const float* be = (const float*)d_in[4];

  cudaFuncSetAttribute(gdn_kernel, cudaFuncAttributeMaxDynamicSharedMemorySize,
                       (int)sizeof(Smem));

  dim3 grid(NBv, BHc);
  gdn_kernel<<<grid, NT, sizeof(Smem)>>>(q, k, v, g, be, (float*)d_out,
                                         (long long)out_size);
}

// round 9
// speedup vs baseline: 1.0034x; 1.0034x over previous
#include <cuda_runtime.h>
#include <cuda_bf16.h>
#include <math.h>

#define NT 512

namespace {

constexpr int Bc  = 2;
constexpr int Hc  = 16;
constexpr int Sc  = 4096;
constexpr int DKc = 128;
constexpr int DVc = 256;
constexpr int Lc  = 64;     // chunk length
constexpr int DVB = 64;     // Dv block per CTA
constexpr int BHc = Bc * Hc;          // 32
constexpr int NCH = Sc / Lc;          // 64 chunks
constexpr int NBv = DVc / DVB;        // 4 Dv blocks

constexpr float kScale = 0.08838834764831845f;   // 128^-0.5
constexpr long long OUT_ELEMS   = (long long)BHc * Sc * DVc;     // 33554432
constexpr long long STATE_ELEMS = (long long)BHc * DKc * DVc;    // 1048576

typedef unsigned long long u64;

// Row swizzle for d-indexed rows (q/k/St): XOR bits [2:5) of the float column
// index by (row>>2)&7. Preserves 16B (LD4) alignment.
__device__ __host__ __forceinline__ int SWZ(int row, int d) {
  return d ^ (((row >> 2) & 7) << 2);
}

struct Smem {
  float q[Lc][DKc];      // normalized q chunk (row-swizzled)
  float k[Lc][DKc];      // normalized k chunk (row-swizzled)
  float v[Lc][DVB];      // v slice; becomes R = gexp*(V - K@S) in place
  float a[Lc][Lc];       // A strict-lower gated (solve input)
  float w[Lc][Lc];       // qkg (gated causal q k^T)
  float t[Lc][Lc];       // T = A^-1 diag(beta)
  float c[Lc][DVB];      // solve scratch P, then correction C
  float St[DVB][DKc];    // running state slice, TRANSPOSED (row-swizzled)
  float part[2][Lc][8];  // norm partial sums
  float ninv[2][Lc];
  float gcum[Lc];
  float gexp[Lc];
  float ginv[Lc];
  float beta[Lc];
};

#define LD4(dst, src) *reinterpret_cast<float4*>(dst) = *reinterpret_cast<const float4*>(src)

// ---- packed f32x2 helpers (Blackwell FFMA2 path, PTX-only) ----------------
__device__ __forceinline__ u64 pk2(float a) {
  u64 r; unsigned int ai = __float_as_uint(a);
  asm("mov.b64 %0, {%1, %1};" : "=l"(r) : "r"(ai));
  return r;
}
__device__ __forceinline__ u64 ffma2(u64 a, u64 b, u64 c) {
  u64 d;
  asm("fma.rn.f32x2 %0, %1, %2, %3;" : "=l"(d) : "l"(a), "l"(b), "l"(c));
  return d;
}
__device__ __forceinline__ float2 upk(u64 a) {
  unsigned int lo, hi;
  asm("mov.b64 {%0, %1}, %2;" : "=r"(lo), "=r"(hi) : "l"(a));
  return make_float2(__uint_as_float(lo), __uint_as_float(hi));
}
__device__ __forceinline__ float foldp(u64 a) {  // sum even/odd-d partials
  float2 f = upk(a);
  return f.x + f.y;
}
// load 16B (4 floats = 2 d-pairs) as two u64 lanes
__device__ __forceinline__ void ld2p(u64 p[2], const float* addr) {
  ulonglong2 t = *reinterpret_cast<const ulonglong2*>(addr);
  p[0] = t.x; p[1] = t.y;
}

// (broadcast-A form for phases E/F)
__device__ __forceinline__ void mm4x4p(u64 acc[4][2], const float Af[4][4],
                                       const u64 Bv[4][2]) {
  #pragma unroll
  for (int r = 0; r < 4; ++r)
    #pragma unroll
    for (int kk = 0; kk < 4; ++kk) {
      u64 pa = pk2(Af[r][kk]);
      acc[r][0] = ffma2(pa, Bv[kk][0], acc[r][0]);
      acc[r][1] = ffma2(pa, Bv[kk][1], acc[r][1]);
    }
}
__device__ __forceinline__ void ldBv(u64 Bv2[2], const float* p) {
  ulonglong2 b = *reinterpret_cast<const ulonglong2*>(p);
  Bv2[0] = b.x; Bv2[1] = b.y;
}

__global__ void __launch_bounds__(NT, 1) gdn_kernel(
    const float* __restrict__ gq, const float* __restrict__ gk,
    const float* __restrict__ gv, const float* __restrict__ gg,
    const float* __restrict__ gb, float* __restrict__ out,
    long long out_elems)
{
  extern __shared__ char smem_raw[];
  Smem& s = *reinterpret_cast<Smem*>(smem_raw);

  const int tid = threadIdx.x;
  const int vb  = blockIdx.x;   // Dv block
  const int bh  = blockIdx.y;   // fused batch*head

  const size_t qkbase = (size_t)bh * Sc * DKc;
  const size_t vbase  = (size_t)bh * Sc * DVc + (size_t)vb * DVB;
  const size_t gbase  = (size_t)bh * Sc;

  for (int i = tid; i < DKc * DVB; i += NT) (&s.St[0][0])[i] = 0.f;
  __syncthreads();

  const int ldrow = tid >> 3;          // q/k load row (0..63)
  const int ldcol = (tid & 7) * 16;    // q/k load col offset
  const int half  = tid >> 8;          // 0: lower (B,G), 1: upper (C,F)
  const int htid  = tid & 255;
  const int hy    = htid >> 4;         // 0..15 (tile row in half-phases)
  const int hx    = htid & 15;         // 0..15 (tile col)

  for (int n = 0; n < NCH; ++n) {
    u64 aI[4][4];   // O_inter accumulators: live only in upper half (C -> F)

    // ================= Phase A: load + normalize q,k; load v,g,beta ========
    const float* qg = gq + qkbase + (size_t)n * Lc * DKc + tid * 16;
    const float* kg = gk + qkbase + (size_t)n * Lc * DKc + tid * 16;
    float4 bq[4], bk[4];
    float sq = 0.f, sk = 0.f;
    #pragma unroll
    for (int u = 0; u < 4; ++u) {
      float4 x = *reinterpret_cast<const float4*>(qg + u * 4);
      float4 y = *reinterpret_cast<const float4*>(kg + u * 4);
      bq[u] = x; bk[u] = y;
      sq += x.x * x.x + x.y * x.y + x.z * x.z + x.w * x.w;
      sk += y.x * y.x + y.y * y.y + y.z * y.z + y.w * y.w;
    }
    s.part[0][ldrow][tid & 7] = sq;
    s.part[1][ldrow][tid & 7] = sk;
    #pragma unroll
    for (int u = 0; u < 2; ++u) {
      int f = tid * 2 + u;
      int r = f >> 4, c4 = (f & 15) * 4;
      LD4(&s.v[r][c4], gv + vbase + (size_t)(n * Lc + r) * DVc + c4);
    }
    if (tid < Lc) {
      s.gcum[tid] = gg[gbase + n * Lc + tid];
      s.beta[tid] = gb[gbase + n * Lc + tid];
    }
    __syncthreads();

    if (tid < 2 * Lc) {
      int w = tid >> 6, r = tid & 63;
      const float* p = s.part[w][r];
      float ssum = ((p[0] + p[1]) + (p[2] + p[3])) + ((p[4] + p[5]) + (p[6] + p[7]));
      s.ninv[w][r] = 1.f / (sqrtf(ssum) + 1e-6f);
    }
    if (tid == 128) {  // sequential cumsum over 64 gates (cheap)
      float acc = 0.f;
      for (int i = 0; i < Lc; ++i) { acc += s.gcum[i]; s.gcum[i] = acc; }
    }
    __syncthreads();

    if (tid < Lc) {
      float e = expf(s.gcum[tid]);
      s.gexp[tid] = e;
      s.ginv[tid] = 1.f / e;
    }
    {
      float iq = s.ninv[0][ldrow], ik = s.ninv[1][ldrow];
      const int swr = ((ldrow >> 2) & 7) << 2;
      #pragma unroll
      for (int u = 0; u < 4; ++u) {
        int cc = (ldcol + u * 4) ^ swr;   // 16B-aligned swizzled column
        float4 x = bq[u];
        x.x *= iq; x.y *= iq; x.z *= iq; x.w *= iq;
        *reinterpret_cast<float4*>(&s.q[ldrow][cc]) = x;
        float4 y = bk[u];
        y.x *= ik; y.y *= ik; y.z *= ik; y.w *= ik;
        *reinterpret_cast<float4*>(&s.k[ldrow][cc]) = y;
      }
    }
    __syncthreads();

    // ===== Phase B (lower half) ∥ Phase C (upper half) =====================
    if (half == 0) {
      // B: A = strict_lower(gated k k^T), qkg = causal(gated q k^T)
      const int i0 = hy * 4, j0 = hx * 4;
      const int sA = (hy & 7) << 2, sB = (hx & 7) << 2;
      u64 aA[4][4] = {}, aQ[4][4] = {};
      #pragma unroll 2
      for (int d = 0; d < DKc; d += 4) {
        u64 Bp[4][2];
        #pragma unroll
        for (int cc = 0; cc < 4; ++cc) ld2p(Bp[cc], &s.k[j0 + cc][d ^ sB]);
        #pragma unroll
        for (int r = 0; r < 4; ++r) {
          u64 Ap[2];
          ld2p(Ap, &s.k[i0 + r][d ^ sA]);
          #pragma unroll
          for (int cc = 0; cc < 4; ++cc) {
            aA[r][cc] = ffma2(Ap[0], Bp[cc][0], aA[r][cc]);
            aA[r][cc] = ffma2(Ap[1], Bp[cc][1], aA[r][cc]);
          }
          ld2p(Ap, &s.q[i0 + r][d ^ sA]);
          #pragma unroll
          for (int cc = 0; cc < 4; ++cc) {
            aQ[r][cc] = ffma2(Ap[0], Bp[cc][0], aQ[r][cc]);
            aQ[r][cc] = ffma2(Ap[1], Bp[cc][1], aQ[r][cc]);
          }
        }
      }
      #pragma unroll
      for (int r = 0; r < 4; ++r) {
        int i = i0 + r;
        float bi = s.beta[i] * s.ginv[i];
        float gi = s.ginv[i];
        #pragma unroll
        for (int cc = 0; cc < 4; ++cc) {
          int j = j0 + cc;
          float fa = foldp(aA[r][cc]);
          float fq = foldp(aQ[r][cc]);
          s.a[i][j] = (j <  i) ? bi * fa * s.gexp[j] : 0.f;
          s.w[i][j] = (j <= i) ? fq * s.gexp[j] * gi : 0.f;
        }
      }
    } else {
      // C: R = gexp*(V - K@St^T) in s.v ; O_inter = Q@St^T kept in aI regs
      const int r0 = hy * 4, c0 = hx * 4;
      const int sA = (hy & 7) << 2, sB = (hx & 7) << 2;
      u64 aK[4][4] = {};
      #pragma unroll
      for (int r = 0; r < 4; ++r)
        #pragma unroll
        for (int cc = 0; cc < 4; ++cc) aI[r][cc] = 0ull;
      #pragma unroll 2
      for (int d = 0; d < DKc; d += 4) {
        u64 Bp[4][2];
        #pragma unroll
        for (int cc = 0; cc < 4; ++cc) ld2p(Bp[cc], &s.St[c0 + cc][d ^ sB]);
        #pragma unroll
        for (int r = 0; r < 4; ++r) {
          u64 Ap[2];
          ld2p(Ap, &s.k[r0 + r][d ^ sA]);
          #pragma unroll
          for (int cc = 0; cc < 4; ++cc) {
            aK[r][cc] = ffma2(Ap[0], Bp[cc][0], aK[r][cc]);
            aK[r][cc] = ffma2(Ap[1], Bp[cc][1], aK[r][cc]);
          }
          ld2p(Ap, &s.q[r0 + r][d ^ sA]);
          #pragma unroll
          for (int cc = 0; cc < 4; ++cc) {
            aI[r][cc] = ffma2(Ap[0], Bp[cc][0], aI[r][cc]);
            aI[r][cc] = ffma2(Ap[1], Bp[cc][1], aI[r][cc]);
          }
        }
      }
      #pragma unroll
      for (int r = 0; r < 4; ++r) {
        float ge = s.gexp[r0 + r];
        float4 vv = *reinterpret_cast<float4*>(&s.v[r0 + r][c0]);
        vv.x = ge * (vv.x - foldp(aK[r][0]));
        vv.y = ge * (vv.y - foldp(aK[r][1]));
        vv.z = ge * (vv.z - foldp(aK[r][2]));
        vv.w = ge * (vv.w - foldp(aK[r][3]));
        *reinterpret_cast<float4*>(&s.v[r0 + r][c0]) = vv;
      }
    }
    __syncthreads();   // s.a/s.w complete, s.v(R) complete

    // ===== Phase D: blocked forward substitution, T = A^-1 diag(beta) ======
    if (tid < Lc) {
      float tc[32];
      #pragma unroll
      for (int i = 0; i < 32; ++i) {
        float v0 = (tid == i) ? s.beta[i] : 0.f;
        float v1 = 0.f, v2 = 0.f, v3 = 0.f;
        int j = 0;
        #pragma unroll
        for (; j + 4 <= i; j += 4) {
          v0 -= s.a[i][j + 0] * tc[j + 0];
          v1 -= s.a[i][j + 1] * tc[j + 1];
          v2 -= s.a[i][j + 2] * tc[j + 2];
          v3 -= s.a[i][j + 3] * tc[j + 3];
        }
        #pragma unroll
        for (; j < i; ++j) v0 -= s.a[i][j] * tc[j];
        float val = (v0 + v1) + (v2 + v3);
        tc[i] = val;
        s.t[i][tid] = val;
      }
    }
    __syncthreads();
    // Off-diagonal: P[32][64] = A[32:64][0:32] @ T[0:32][:]  (all 512 threads,
    // 4 outputs each: 4 rows x 1 column)
    {
      const int rp0 = (tid >> 6) * 4;   // 0..28
      const int cp  = tid & 63;         // 0..63
      float accP[4] = {};
      #pragma unroll
      for (int j = 0; j < 32; j += 4) {
        float tv[4];
        #pragma unroll
        for (int jj = 0; jj < 4; ++jj) tv[jj] = s.t[j + jj][cp];
        #pragma unroll
        for (int r = 0; r < 4; ++r) {
          float4 av = *reinterpret_cast<const float4*>(&s.a[32 + rp0 + r][j]);
          accP[r] += av.x * tv[0] + av.y * tv[1] + av.z * tv[2] + av.w * tv[3];
        }
      }
      #pragma unroll
      for (int r = 0; r < 4; ++r) s.c[rp0 + r][cp] = accP[r];
    }
    __syncthreads();
    // Block 1: rows 32..63 (4-accumulator ILP)
    if (tid < Lc) {
      float tc[32];
      #pragma unroll
      for (int i = 0; i < 32; ++i) {
        int gi = 32 + i;
        float v0 = ((tid == gi) ? s.beta[gi] : 0.f) - s.c[i][tid];
        float v1 = 0.f, v2 = 0.f, v3 = 0.f;
        int j = 0;
        #pragma unroll
        for (; j + 4 <= i; j += 4) {
          v0 -= s.a[gi][32 + j + 0] * tc[j + 0];
          v1 -= s.a[gi][32 + j + 1] * tc[j + 1];
          v2 -= s.a[gi][32 + j + 2] * tc[j + 2];
          v3 -= s.a[gi][32 + j + 3] * tc[j + 3];
        }
        #pragma unroll
        for (; j < i; ++j) v0 -= s.a[gi][32 + j] * tc[j];
        float val = (v0 + v1) + (v2 + v3);
        tc[i] = val;
        s.t[gi][tid] = val;
      }
    }
    __syncthreads();

    // ===== Phase E: C = T @ R  (all 512 threads, 2x4 tiles, triangular) ====
    {
      const int i0 = (tid >> 4) * 2;    // 0..62
      const int c0 = (tid & 15) * 4;
      u64 aC[2][2] = {};
      #pragma unroll 2
      for (int j = 0; j <= i0; j += 4) {
        u64 Bv[4][2];
        #pragma unroll
        for (int jj = 0; jj < 4; ++jj) ldBv(Bv[jj], &s.v[j + jj][c0]);
        float Af[2][4];
        #pragma unroll
        for (int r = 0; r < 2; ++r) LD4(&Af[r][0], &s.t[i0 + r][j]);
        #pragma unroll
        for (int r = 0; r < 2; ++r)
          #pragma unroll
          for (int kk = 0; kk < 4; ++kk) {
            u64 pa = pk2(Af[r][kk]);
            aC[r][0] = ffma2(pa, Bv[kk][0], aC[r][0]);
            aC[r][1] = ffma2(pa, Bv[kk][1], aC[r][1]);
          }
      }
      #pragma unroll
      for (int r = 0; r < 2; ++r) {
        float2 f0 = upk(aC[r][0]), f1 = upk(aC[r][1]);
        *reinterpret_cast<float4*>(&s.c[i0 + r][c0]) =
            make_float4(f0.x, f0.y, f1.x, f1.y);
      }
    }
    __syncthreads();

    // ===== Phase F (upper half) ∥ Phase G (lower half) =====================
    if (half == 1) {
      // F: O = kScale*(gexp_i * aI + qkg @ C), store to gmem
      const int i0 = hy * 4, c0 = hx * 4;
      u64 aO[4][2] = {};
      #pragma unroll 2
      for (int j = 0; j <= i0; j += 4) {
        u64 Bv[4][2];
        #pragma unroll
        for (int jj = 0; jj < 4; ++jj) ldBv(Bv[jj], &s.c[j + jj][c0]);
        float Af[4][4];
        #pragma unroll
        for (int r = 0; r < 4; ++r) LD4(&Af[r][0], &s.w[i0 + r][j]);
        mm4x4p(aO, Af, Bv);
      }
      const size_t obase = ((size_t)bh * Sc + (size_t)n * Lc) * DVc + (size_t)vb * DVB;
      #pragma unroll
      for (int r = 0; r < 4; ++r) {
        int i = i0 + r;
        float ge = s.gexp[i];
        float2 o0 = upk(aO[r][0]), o1 = upk(aO[r][1]);
        float2 q0 = upk(aI[r][0]), q1 = upk(aI[r][1]);
        float2 q2 = upk(aI[r][2]), q3 = upk(aI[r][3]);
        float4 o;
        o.x = kScale * (ge * (q0.x + q0.y) + o0.x);
        o.y = kScale * (ge * (q1.x + q1.y) + o0.y);
        o.z = kScale * (ge * (q2.x + q2.y) + o1.x);
        o.w = kScale * (ge * (q3.x + q3.y) + o1.y);
        *reinterpret_cast<float4*>(&out[obase + (size_t)i * DVc + c0]) = o;
      }
    } else {
      // G: St[c][d] = egt*St[c][d] + sum_i (gexp_i C[i][c]) k[i][d]
      const int c0 = (tid & 15) * 4;
      const int d0 = (tid >> 4) * 8;
      const int sc = ((tid & 15) & 7) << 2;  // swizzle for St rows c0..c0+3
      const float egt = s.gexp[Lc - 1];
      const u64 egt2 = pk2(egt);
      u64 acc[4][4] = {};
      #pragma unroll 2
      for (int i = 0; i < Lc; ++i) {
        const int si = ((i >> 2) & 7) << 2;
        u64 kp[4];
        ld2p(kp,     &s.k[i][d0 ^ si]);
        ld2p(kp + 2, &s.k[i][(d0 + 4) ^ si]);
        float4 cv = *reinterpret_cast<const float4*>(&s.c[i][c0]);
        float ge = s.gexp[i];
        u64 gc0 = pk2(ge * cv.x), gc1 = pk2(ge * cv.y);
        u64 gc2 = pk2(ge * cv.z), gc3 = pk2(ge * cv.w);
        #pragma unroll
        for (int dp = 0; dp < 4; ++dp) {
          acc[0][dp] = ffma2(gc0, kp[dp], acc[0][dp]);
          acc[1][dp] = ffma2(gc1, kp[dp], acc[1][dp]);
          acc[2][dp] = ffma2(gc2, kp[dp], acc[2][dp]);
          acc[3][dp] = ffma2(gc3, kp[dp], acc[3][dp]);
        }
      }
      #pragma unroll
      for (int cc = 0; cc < 4; ++cc) {
        float* row = &s.St[c0 + cc][0];
        u64* p0 = reinterpret_cast<u64*>(row + (d0 ^ sc));
        u64* p1 = reinterpret_cast<u64*>(row + ((d0 + 4) ^ sc));
        p0[0] = ffma2(p0[0], egt2, acc[cc][0]);
        p0[1] = ffma2(p0[1], egt2, acc[cc][1]);
        p1[0] = ffma2(p1[0], egt2, acc[cc][2]);
        p1[1] = ffma2(p1[1], egt2, acc[cc][3]);
      }
    }
    __syncthreads();
  }  // chunk loop

  // Final state (second tuple element), if the output buffer includes it.
  if (out_elems >= OUT_ELEMS + STATE_ELEMS) {
    float* st = out + OUT_ELEMS + (size_t)bh * DKc * DVc + (size_t)vb * DVB;
    for (int f = tid; f < DKc * DVB; f += NT) {
      int d = f >> 6;        // 0..127
      int c = f & 63;        // 0..63 (contiguous for coalescing)
      st[(size_t)d * DVc + c] = s.St[c][SWZ(c, d)];
    }
  }
}

}  // namespace

extern "C" void kernel_launch(void* const* d_in, const int* in_sizes, int n_in,
                              void* d_out, int out_size) {
  (void)in_sizes; (void)n_in;
  const float* q  = (const float*)d_in[0];
  const float* k  = (const float*)d_in[1];
  const float* v  = (const float*)d_in[2];
  const float* g  = (const float*)d_in[3];
  const float* be = (const float*)d_in[4];

  cudaFuncSetAttribute(gdn_kernel, cudaFuncAttributeMaxDynamicSharedMemorySize,
                       (int)sizeof(Smem));

  dim3 grid(NBv, BHc);
  gdn_kernel<<<grid, NT, sizeof(Smem)>>>(q, k, v, g, be, (float*)d_out,
                                         (long long)out_size);
}

// round 11
// speedup vs baseline: 1.0371x; 1.0335x over previous
#include <cuda_runtime.h>
#include <cuda_bf16.h>
#include <math.h>

#define NT 512

namespace {

constexpr int Bc  = 2;
constexpr int Hc  = 16;
constexpr int Sc  = 4096;
constexpr int DKc = 128;
constexpr int DVc = 256;
constexpr int Lc  = 64;     // chunk length
constexpr int DVB = 64;     // Dv block per CTA
constexpr int BHc = Bc * Hc;          // 32
constexpr int NCH = Sc / Lc;          // 64 chunks
constexpr int NBv = DVc / DVB;        // 4 Dv blocks

constexpr float kScale = 0.08838834764831845f;   // 128^-0.5
constexpr long long OUT_ELEMS   = (long long)BHc * Sc * DVc;     // 33554432
constexpr long long STATE_ELEMS = (long long)BHc * DKc * DVc;    // 1048576

typedef unsigned long long u64;

// Row swizzle for d-indexed rows (q/k/St): XOR bits [2:5) of the float column
// index by (row>>2)&7. Preserves 16B (LD4) alignment.
__device__ __host__ __forceinline__ int SWZ(int row, int d) {
  return d ^ (((row >> 2) & 7) << 2);
}

struct Smem {
  float q[Lc][DKc];      // normalized q chunk (row-swizzled)
  float k[Lc][DKc];      // normalized k chunk (row-swizzled)
  float v[Lc][DVB];      // v slice; becomes R = gexp*(V - K@S) in place
  float a[Lc][Lc];       // A strict-lower gated (solve input)
  float w[Lc][Lc];       // qkg (gated causal q k^T)
  float t[Lc][Lc];       // T = A^-1 diag(beta)
  float c[Lc][DVB];      // solve scratch P, then correction C
  float oi[Lc][DVB];     // gexp_i * (Q @ St^T)  (O_inter, staged for F)
  float St[DVB][DKc];    // running state slice, TRANSPOSED (row-swizzled)
  float part[2][Lc][8];  // norm partial sums
  float ninv[2][Lc];
  float gcum[Lc];
  float gexp[Lc];
  float ginv[Lc];
  float beta[Lc];
};

#define LD4(dst, src) *reinterpret_cast<float4*>(dst) = *reinterpret_cast<const float4*>(src)

// ---- packed f32x2 helpers (Blackwell FFMA2 path, PTX-only) ----------------
__device__ __forceinline__ u64 pk2(float a) {
  u64 r; unsigned int ai = __float_as_uint(a);
  asm("mov.b64 %0, {%1, %1};" : "=l"(r) : "r"(ai));
  return r;
}
__device__ __forceinline__ u64 ffma2(u64 a, u64 b, u64 c) {
  u64 d;
  asm("fma.rn.f32x2 %0, %1, %2, %3;" : "=l"(d) : "l"(a), "l"(b), "l"(c));
  return d;
}
__device__ __forceinline__ float2 upk(u64 a) {
  unsigned int lo, hi;
  asm("mov.b64 {%0, %1}, %2;" : "=r"(lo), "=r"(hi) : "l"(a));
  return make_float2(__uint_as_float(lo), __uint_as_float(hi));
}
__device__ __forceinline__ float foldp(u64 a) {  // sum even/odd-d partials
  float2 f = upk(a);
  return f.x + f.y;
}
// load 16B (4 floats = 2 d-pairs) as two u64 lanes
__device__ __forceinline__ void ld2p(u64 p[2], const float* addr) {
  ulonglong2 t = *reinterpret_cast<const ulonglong2*>(addr);
  p[0] = t.x; p[1] = t.y;
}

// (broadcast-A form for phases E/F)
__device__ __forceinline__ void mm4x4p(u64 acc[4][2], const float Af[4][4],
                                       const u64 Bv[4][2]) {
  #pragma unroll
  for (int r = 0; r < 4; ++r)
    #pragma unroll
    for (int kk = 0; kk < 4; ++kk) {
      u64 pa = pk2(Af[r][kk]);
      acc[r][0] = ffma2(pa, Bv[kk][0], acc[r][0]);
      acc[r][1] = ffma2(pa, Bv[kk][1], acc[r][1]);
    }
}
__device__ __forceinline__ void ldBv(u64 Bv2[2], const float* p) {
  ulonglong2 b = *reinterpret_cast<const ulonglong2*>(p);
  Bv2[0] = b.x; Bv2[1] = b.y;
}

// Single-accumulator 4x4-tile GEMM pass over the d (reduction) axis.
// A rows at (arows)[i0+r][.], B rows at (brows)[j0+cc][.], both row-swizzled.
__device__ __forceinline__ void gemm_pass_4x4(
    u64 acc[4][4], const float (*arows)[DKc], const float (*brows)[DKc],
    int i0, int j0, int sA, int sB) {
  #pragma unroll 2
  for (int d = 0; d < DKc; d += 4) {
    u64 Bp[4][2];
    #pragma unroll
    for (int cc = 0; cc < 4; ++cc) ld2p(Bp[cc], &brows[j0 + cc][d ^ sB]);
    #pragma unroll
    for (int r = 0; r < 4; ++r) {
      u64 Ap[2];
      ld2p(Ap, &arows[i0 + r][d ^ sA]);
      #pragma unroll
      for (int cc = 0; cc < 4; ++cc) {
        acc[r][cc] = ffma2(Ap[0], Bp[cc][0], acc[r][cc]);
        acc[r][cc] = ffma2(Ap[1], Bp[cc][1], acc[r][cc]);
      }
    }
  }
}

__global__ void __launch_bounds__(NT, 1) gdn_kernel(
    const float* __restrict__ gq, const float* __restrict__ gk,
    const float* __restrict__ gv, const float* __restrict__ gg,
    const float* __restrict__ gb, float* __restrict__ out,
    long long out_elems)
{
  extern __shared__ char smem_raw[];
  Smem& s = *reinterpret_cast<Smem*>(smem_raw);

  const int tid = threadIdx.x;
  const int vb  = blockIdx.x;   // Dv block
  const int bh  = blockIdx.y;   // fused batch*head

  const size_t qkbase = (size_t)bh * Sc * DKc;
  const size_t vbase  = (size_t)bh * Sc * DVc + (size_t)vb * DVB;
  const size_t gbase  = (size_t)bh * Sc;

  for (int i = tid; i < DKc * DVB; i += NT) (&s.St[0][0])[i] = 0.f;
  __syncthreads();

  const int ldrow = tid >> 3;          // q/k load row (0..63)
  const int ldcol = (tid & 7) * 16;    // q/k load col offset
  const int half  = tid >> 8;          // 0: lower (B,G), 1: upper (C,F)
  const int htid  = tid & 255;
  const int hy    = htid >> 4;         // 0..15 (tile row in half-phases)
  const int hx    = htid & 15;         // 0..15 (tile col)

  for (int n = 0; n < NCH; ++n) {
    // ================= Phase A: load + normalize q,k; load v,g,beta ========
    const float* qg = gq + qkbase + (size_t)n * Lc * DKc + tid * 16;
    const float* kg = gk + qkbase + (size_t)n * Lc * DKc + tid * 16;
    float4 bq[4], bk[4];
    float sq = 0.f, sk = 0.f;
    #pragma unroll
    for (int u = 0; u < 4; ++u) {
      float4 x = *reinterpret_cast<const float4*>(qg + u * 4);
      float4 y = *reinterpret_cast<const float4*>(kg + u * 4);
      bq[u] = x; bk[u] = y;
      sq += x.x * x.x + x.y * x.y + x.z * x.z + x.w * x.w;
      sk += y.x * y.x + y.y * y.y + y.z * y.z + y.w * y.w;
    }
    s.part[0][ldrow][tid & 7] = sq;
    s.part[1][ldrow][tid & 7] = sk;
    #pragma unroll
    for (int u = 0; u < 2; ++u) {
      int f = tid * 2 + u;
      int r = f >> 4, c4 = (f & 15) * 4;
      LD4(&s.v[r][c4], gv + vbase + (size_t)(n * Lc + r) * DVc + c4);
    }
    if (tid < Lc) {
      s.gcum[tid] = gg[gbase + n * Lc + tid];
      s.beta[tid] = gb[gbase + n * Lc + tid];
    }
    __syncthreads();

    if (tid < 2 * Lc) {
      int w = tid >> 6, r = tid & 63;
      const float* p = s.part[w][r];
      float ssum = ((p[0] + p[1]) + (p[2] + p[3])) + ((p[4] + p[5]) + (p[6] + p[7]));
      s.ninv[w][r] = 1.f / (sqrtf(ssum) + 1e-6f);
    }
    if (tid == 128) {  // sequential cumsum over 64 gates (cheap)
      float acc = 0.f;
      for (int i = 0; i < Lc; ++i) { acc += s.gcum[i]; s.gcum[i] = acc; }
    }
    __syncthreads();

    if (tid < Lc) {
      float e = expf(s.gcum[tid]);
      s.gexp[tid] = e;
      s.ginv[tid] = 1.f / e;
    }
    {
      float iq = s.ninv[0][ldrow], ik = s.ninv[1][ldrow];
      const int swr = ((ldrow >> 2) & 7) << 2;
      #pragma unroll
      for (int u = 0; u < 4; ++u) {
        int cc = (ldcol + u * 4) ^ swr;   // 16B-aligned swizzled column
        float4 x = bq[u];
        x.x *= iq; x.y *= iq; x.z *= iq; x.w *= iq;
        *reinterpret_cast<float4*>(&s.q[ldrow][cc]) = x;
        float4 y = bk[u];
        y.x *= ik; y.y *= ik; y.z *= ik; y.w *= ik;
        *reinterpret_cast<float4*>(&s.k[ldrow][cc]) = y;
      }
    }
    __syncthreads();

    // ===== Phase B (lower half) ∥ Phase C (upper half), two passes each ====
    if (half == 0) {
      const int i0 = hy * 4, j0 = hx * 4;
      const int sA = (hy & 7) << 2, sB = (hx & 7) << 2;
      {  // B pass 1: A = strict_lower( beta_i*ginv_i * (k k^T) * gexp_j )
        u64 aA[4][4] = {};
        gemm_pass_4x4(aA, s.k, s.k, i0, j0, sA, sB);
        #pragma unroll
        for (int r = 0; r < 4; ++r) {
          int i = i0 + r;
          float bi = s.beta[i] * s.ginv[i];
          float4 ra;
          ra.x = (j0 + 0 < i) ? bi * foldp(aA[r][0]) * s.gexp[j0 + 0] : 0.f;
          ra.y = (j0 + 1 < i) ? bi * foldp(aA[r][1]) * s.gexp[j0 + 1] : 0.f;
          ra.z = (j0 + 2 < i) ? bi * foldp(aA[r][2]) * s.gexp[j0 + 2] : 0.f;
          ra.w = (j0 + 3 < i) ? bi * foldp(aA[r][3]) * s.gexp[j0 + 3] : 0.f;
          *reinterpret_cast<float4*>(&s.a[i][j0]) = ra;
        }
      }
      {  // B pass 2: qkg = causal( (q k^T) * gexp_j * ginv_i )
        u64 aQ[4][4] = {};
        gemm_pass_4x4(aQ, s.q, s.k, i0, j0, sA, sB);
        #pragma unroll
        for (int r = 0; r < 4; ++r) {
          int i = i0 + r;
          float gi = s.ginv[i];
          float4 rw;
          rw.x = (j0 + 0 <= i) ? foldp(aQ[r][0]) * s.gexp[j0 + 0] * gi : 0.f;
          rw.y = (j0 + 1 <= i) ? foldp(aQ[r][1]) * s.gexp[j0 + 1] * gi : 0.f;
          rw.z = (j0 + 2 <= i) ? foldp(aQ[r][2]) * s.gexp[j0 + 2] * gi : 0.f;
          rw.w = (j0 + 3 <= i) ? foldp(aQ[r][3]) * s.gexp[j0 + 3] * gi : 0.f;
          *reinterpret_cast<float4*>(&s.w[i][j0]) = rw;
        }
      }
    } else {
      const int r0 = hy * 4, c0 = hx * 4;
      const int sA = (hy & 7) << 2, sB = (hx & 7) << 2;
      {  // C pass 1: R = gexp_i * (V - K@St^T), in place in s.v
        u64 aK[4][4] = {};
        gemm_pass_4x4(aK, s.k, s.St, r0, c0, sA, sB);
        #pragma unroll
        for (int r = 0; r < 4; ++r) {
          float ge = s.gexp[r0 + r];
          float4 vv = *reinterpret_cast<float4*>(&s.v[r0 + r][c0]);
          vv.x = ge * (vv.x - foldp(aK[r][0]));
          vv.y = ge * (vv.y - foldp(aK[r][1]));
          vv.z = ge * (vv.z - foldp(aK[r][2]));
          vv.w = ge * (vv.w - foldp(aK[r][3]));
          *reinterpret_cast<float4*>(&s.v[r0 + r][c0]) = vv;
        }
      }
      {  // C pass 2: oi = gexp_i * (Q@St^T), staged in smem for F
        u64 aI[4][4] = {};
        gemm_pass_4x4(aI, s.q, s.St, r0, c0, sA, sB);
        #pragma unroll
        for (int r = 0; r < 4; ++r) {
          float ge = s.gexp[r0 + r];
          float4 ro;
          ro.x = ge * foldp(aI[r][0]);
          ro.y = ge * foldp(aI[r][1]);
          ro.z = ge * foldp(aI[r][2]);
          ro.w = ge * foldp(aI[r][3]);
          *reinterpret_cast<float4*>(&s.oi[r0 + r][c0]) = ro;
        }
      }
    }
    __syncthreads();   // s.a/s.w complete, s.v(R) complete, s.oi complete

    // ===== Phase D: blocked forward substitution, T = A^-1 diag(beta) ======
    if (tid < Lc) {
      float tc[32];
      #pragma unroll
      for (int i = 0; i < 32; ++i) {
        float v0 = (tid == i) ? s.beta[i] : 0.f;
        float v1 = 0.f, v2 = 0.f, v3 = 0.f;
        int j = 0;
        #pragma unroll
        for (; j + 4 <= i; j += 4) {
          v0 -= s.a[i][j + 0] * tc[j + 0];
          v1 -= s.a[i][j + 1] * tc[j + 1];
          v2 -= s.a[i][j + 2] * tc[j + 2];
          v3 -= s.a[i][j + 3] * tc[j + 3];
        }
        #pragma unroll
        for (; j < i; ++j) v0 -= s.a[i][j] * tc[j];
        float val = (v0 + v1) + (v2 + v3);
        tc[i] = val;
        s.t[i][tid] = val;
      }
    }
    __syncthreads();
    // Off-diagonal: P[32][64] = A[32:64][0:32] @ T[0:32][:]  (all 512 threads,
    // 4 outputs each: 4 rows x 1 column)
    {
      const int rp0 = (tid >> 6) * 4;   // 0..28
      const int cp  = tid & 63;         // 0..63
      float accP[4] = {};
      #pragma unroll
      for (int j = 0; j < 32; j += 4) {
        float tv[4];
        #pragma unroll
        for (int jj = 0; jj < 4; ++jj) tv[jj] = s.t[j + jj][cp];
        #pragma unroll
        for (int r = 0; r < 4; ++r) {
          float4 av = *reinterpret_cast<const float4*>(&s.a[32 + rp0 + r][j]);
          accP[r] += av.x * tv[0] + av.y * tv[1] + av.z * tv[2] + av.w * tv[3];
        }
      }
      #pragma unroll
      for (int r = 0; r < 4; ++r) s.c[rp0 + r][cp] = accP[r];
    }
    __syncthreads();
    // Block 1: rows 32..63 (4-accumulator ILP)
    if (tid < Lc) {
      float tc[32];
      #pragma unroll
      for (int i = 0; i < 32; ++i) {
        int gi = 32 + i;
        float v0 = ((tid == gi) ? s.beta[gi] : 0.f) - s.c[i][tid];
        float v1 = 0.f, v2 = 0.f, v3 = 0.f;
        int j = 0;
        #pragma unroll
        for (; j + 4 <= i; j += 4) {
          v0 -= s.a[gi][32 + j + 0] * tc[j + 0];
          v1 -= s.a[gi][32 + j + 1] * tc[j + 1];
          v2 -= s.a[gi][32 + j + 2] * tc[j + 2];
          v3 -= s.a[gi][32 + j + 3] * tc[j + 3];
        }
        #pragma unroll
        for (; j < i; ++j) v0 -= s.a[gi][32 + j] * tc[j];
        float val = (v0 + v1) + (v2 + v3);
        tc[i] = val;
        s.t[gi][tid] = val;
      }
    }
    __syncthreads();

    // ===== Phase E: C = T @ R  (all 512 threads, 2x4 tiles, triangular) ====
    {
      const int i0 = (tid >> 4) * 2;    // 0..62
      const int c0 = (tid & 15) * 4;
      u64 aC[2][2] = {};
      #pragma unroll 2
      for (int j = 0; j <= i0; j += 4) {
        u64 Bv[4][2];
        #pragma unroll
        for (int jj = 0; jj < 4; ++jj) ldBv(Bv[jj], &s.v[j + jj][c0]);
        float Af[2][4];
        #pragma unroll
        for (int r = 0; r < 2; ++r) LD4(&Af[r][0], &s.t[i0 + r][j]);
        #pragma unroll
        for (int r = 0; r < 2; ++r)
          #pragma unroll
          for (int kk = 0; kk < 4; ++kk) {
            u64 pa = pk2(Af[r][kk]);
            aC[r][0] = ffma2(pa, Bv[kk][0], aC[r][0]);
            aC[r][1] = ffma2(pa, Bv[kk][1], aC[r][1]);
          }
      }
      #pragma unroll
      for (int r = 0; r < 2; ++r) {
        float2 f0 = upk(aC[r][0]), f1 = upk(aC[r][1]);
        *reinterpret_cast<float4*>(&s.c[i0 + r][c0]) =
            make_float4(f0.x, f0.y, f1.x, f1.y);
      }
    }
    __syncthreads();

    // ===== Phase F (upper half) ∥ Phase G (lower half) =====================
    if (half == 1) {
      // F: O = kScale*(oi + qkg @ C), store to gmem
      const int i0 = hy * 4, c0 = hx * 4;
      u64 aO[4][2] = {};
      #pragma unroll 2
      for (int j = 0; j <= i0; j += 4) {
        u64 Bv[4][2];
        #pragma unroll
        for (int jj = 0; jj < 4; ++jj) ldBv(Bv[jj], &s.c[j + jj][c0]);
        float Af[4][4];
        #pragma unroll
        for (int r = 0; r < 4; ++r) LD4(&Af[r][0], &s.w[i0 + r][j]);
        mm4x4p(aO, Af, Bv);
      }
      const size_t obase = ((size_t)bh * Sc + (size_t)n * Lc) * DVc + (size_t)vb * DVB;
      #pragma unroll
      for (int r = 0; r < 4; ++r) {
        int i = i0 + r;
        float2 o0 = upk(aO[r][0]), o1 = upk(aO[r][1]);
        float4 oi4 = *reinterpret_cast<const float4*>(&s.oi[i][c0]);
        float4 o;
        o.x = kScale * (oi4.x + o0.x);
        o.y = kScale * (oi4.y + o0.y);
        o.z = kScale * (oi4.z + o1.x);
        o.w = kScale * (oi4.w + o1.y);
        *reinterpret_cast<float4*>(&out[obase + (size_t)i * DVc + c0]) = o;
      }
    } else {
      // G: St[c][d] = egt*St[c][d] + sum_i (gexp_i C[i][c]) k[i][d]
      const int c0 = (tid & 15) * 4;
      const int d0 = (tid >> 4) * 8;
      const int sc = ((tid & 15) & 7) << 2;  // swizzle for St rows c0..c0+3
      const float egt = s.gexp[Lc - 1];
      const u64 egt2 = pk2(egt);
      u64 acc[4][4] = {};
      #pragma unroll 2
      for (int i = 0; i < Lc; ++i) {
        const int si = ((i >> 2) & 7) << 2;
        u64 kp[4];
        ld2p(kp,     &s.k[i][d0 ^ si]);
        ld2p(kp + 2, &s.k[i][(d0 + 4) ^ si]);
        float4 cv = *reinterpret_cast<const float4*>(&s.c[i][c0]);
        float ge = s.gexp[i];
        u64 gc0 = pk2(ge * cv.x), gc1 = pk2(ge * cv.y);
        u64 gc2 = pk2(ge * cv.z), gc3 = pk2(ge * cv.w);
        #pragma unroll
        for (int dp = 0; dp < 4; ++dp) {
          acc[0][dp] = ffma2(gc0, kp[dp], acc[0][dp]);
          acc[1][dp] = ffma2(gc1, kp[dp], acc[1][dp]);
          acc[2][dp] = ffma2(gc2, kp[dp], acc[2][dp]);
          acc[3][dp] = ffma2(gc3, kp[dp], acc[3][dp]);
        }
      }
      #pragma unroll
      for (int cc = 0; cc < 4; ++cc) {
        float* row = &s.St[c0 + cc][0];
        u64* p0 = reinterpret_cast<u64*>(row + (d0 ^ sc));
        u64* p1 = reinterpret_cast<u64*>(row + ((d0 + 4) ^ sc));
        p0[0] = ffma2(p0[0], egt2, acc[cc][0]);
        p0[1] = ffma2(p0[1], egt2, acc[cc][1]);
        p1[0] = ffma2(p1[0], egt2, acc[cc][2]);
        p1[1] = ffma2(p1[1], egt2, acc[cc][3]);
      }
    }
    __syncthreads();
  }  // chunk loop

  // Final state (second tuple element), if the output buffer includes it.
  if (out_elems >= OUT_ELEMS + STATE_ELEMS) {
    float* st = out + OUT_ELEMS + (size_t)bh * DKc * DVc + (size_t)vb * DVB;
    for (int f = tid; f < DKc * DVB; f += NT) {
      int d = f >> 6;        // 0..127
      int c = f & 63;        // 0..63 (contiguous for coalescing)
      st[(size_t)d * DVc + c] = s.St[c][SWZ(c, d)];
    }
  }
}

}  // namespace

extern "C" void kernel_launch(void* const* d_in, const int* in_sizes, int n_in,
                              void* d_out, int out_size) {
  (void)in_sizes; (void)n_in;
  const float* q  = (const float*)d_in[0];
  const float* k  = (const float*)d_in[1];
  const float* v  = (const float*)d_in[2];
  const float* g  = (const float*)d_in[3];
  const float* be = (const float*)d_in[4];

  cudaFuncSetAttribute(gdn_kernel, cudaFuncAttributeMaxDynamicSharedMemorySize,
                       (int)sizeof(Smem));

  dim3 grid(NBv, BHc);
  gdn_kernel<<<grid, NT, sizeof(Smem)>>>(q, k, v, g, be, (float*)d_out,
                                         (long long)out_size);
}

// round 13
// speedup vs baseline: 1.3142x; 1.2673x over previous
#include <cuda_runtime.h>
#include <cuda_bf16.h>
#include <math.h>

namespace {

constexpr int Bc  = 2;
constexpr int Hc  = 16;
constexpr int Sc  = 4096;
constexpr int DKc = 128;
constexpr int DVc = 256;
constexpr int Lc  = 64;
constexpr int DVB = 64;
constexpr int BHc = Bc * Hc;          // 32
constexpr int NCH = Sc / Lc;          // 64
constexpr int NBv = DVc / DVB;        // 4

constexpr float kScale = 0.08838834764831845f;   // 128^-0.5
constexpr long long OUT_ELEMS   = (long long)BHc * Sc * DVc;
constexpr long long STATE_ELEMS = (long long)BHc * DKc * DVc;

typedef unsigned long long u64;

// ---------------- gmem scratch (precompute -> scan) ------------------------
__device__ float g_qhat[(size_t)BHc * Sc * DKc];   // gexp ∘ q_norm
__device__ float g_kg  [(size_t)BHc * Sc * DKc];   // gexp ∘ k_norm
__device__ float g_W   [(size_t)BHc * Sc * DKc];   // T @ kg
__device__ float g_U0  [(size_t)BHc * Sc * DVc];   // T @ (gexp ∘ v)
__device__ float g_qkg [(size_t)BHc * Sc * Lc];    // gated causal q k^T
__device__ float g_egt [BHc * NCH];                // exp(g_total) per chunk

__device__ __host__ __forceinline__ int SWZ(int row, int d) {
  return d ^ (((row >> 2) & 7) << 2);
}

#define LD4(dst, src) *reinterpret_cast<float4*>(dst) = *reinterpret_cast<const float4*>(src)

// ---- packed f32x2 helpers -------------------------------------------------
__device__ __forceinline__ u64 pk2(float a) {
  u64 r; unsigned int ai = __float_as_uint(a);
  asm("mov.b64 %0, {%1, %1};" : "=l"(r) : "r"(ai));
  return r;
}
__device__ __forceinline__ u64 ffma2(u64 a, u64 b, u64 c) {
  u64 d;
  asm("fma.rn.f32x2 %0, %1, %2, %3;" : "=l"(d) : "l"(a), "l"(b), "l"(c));
  return d;
}
__device__ __forceinline__ float2 upk(u64 a) {
  unsigned int lo, hi;
  asm("mov.b64 {%0, %1}, %2;" : "=r"(lo), "=r"(hi) : "l"(a));
  return make_float2(__uint_as_float(lo), __uint_as_float(hi));
}
__device__ __forceinline__ float foldp(u64 a) {
  float2 f = upk(a);
  return f.x + f.y;
}
__device__ __forceinline__ void ld2p(u64* p, const float* addr) {
  ulonglong2 t = *reinterpret_cast<const ulonglong2*>(addr);
  p[0] = t.x; p[1] = t.y;
}
__device__ __forceinline__ void mm4x4p(u64 acc[4][2], const float Af[4][4],
                                       const u64 Bv[4][2]) {
  #pragma unroll
  for (int r = 0; r < 4; ++r)
    #pragma unroll
    for (int kk = 0; kk < 4; ++kk) {
      u64 pa = pk2(Af[r][kk]);
      acc[r][0] = ffma2(pa, Bv[kk][0], acc[r][0]);
      acc[r][1] = ffma2(pa, Bv[kk][1], acc[r][1]);
    }
}
__device__ __forceinline__ void ldBv(u64 Bv2[2], const float* p) {
  ulonglong2 b = *reinterpret_cast<const ulonglong2*>(p);
  Bv2[0] = b.x; Bv2[1] = b.y;
}

// d-pair packed single-accumulator 4x4 GEMM pass (reduction over d=0..127).
__device__ __forceinline__ void gemm_pass_4x4(
    u64 acc[4][4], const float (*arows)[DKc], const float (*brows)[DKc],
    int i0, int j0, int sA, int sB) {
  #pragma unroll 2
  for (int d = 0; d < DKc; d += 4) {
    u64 Bp[4][2];
    #pragma unroll
    for (int cc = 0; cc < 4; ++cc) ld2p(Bp[cc], &brows[j0 + cc][d ^ sB]);
    #pragma unroll
    for (int r = 0; r < 4; ++r) {
      u64 Ap[2];
      ld2p(Ap, &arows[i0 + r][d ^ sA]);
      #pragma unroll
      for (int cc = 0; cc < 4; ++cc) {
        acc[r][cc] = ffma2(Ap[0], Bp[cc][0], acc[r][cc]);
        acc[r][cc] = ffma2(Ap[1], Bp[cc][1], acc[r][cc]);
      }
    }
  }
}

// out[i][c] = sum_{j<=i} T[i][j]*B[j][c], rows i0..i0+3, cols c0..c0+7.
// B rows are swizzled d-indexed rows; out goes to gmem with row stride gstride.
__device__ __forceinline__ void tri_mm(
    const float (*T)[Lc], const float (*B)[DKc], float* gout,
    int gstride, int i0, int c0) {
  u64 acc[4][4] = {};
  #pragma unroll 2
  for (int j = 0; j <= i0; j += 4) {
    u64 Bp[4][4];
    #pragma unroll
    for (int jj = 0; jj < 4; ++jj) {
      int sj = (((j + jj) >> 2) & 7) << 2;
      ld2p(&Bp[jj][0], &B[j + jj][c0 ^ sj]);
      ld2p(&Bp[jj][2], &B[j + jj][(c0 + 4) ^ sj]);
    }
    #pragma unroll
    for (int r = 0; r < 4; ++r) {
      float Tf[4];
      LD4(Tf, &T[i0 + r][j]);
      #pragma unroll
      for (int jj = 0; jj < 4; ++jj) {
        u64 pa = pk2(Tf[jj]);
        #pragma unroll
        for (int dp = 0; dp < 4; ++dp)
          acc[r][dp] = ffma2(pa, Bp[jj][dp], acc[r][dp]);
      }
    }
  }
  #pragma unroll
  for (int r = 0; r < 4; ++r) {
    float2 f0 = upk(acc[r][0]), f1 = upk(acc[r][1]);
    float2 f2 = upk(acc[r][2]), f3 = upk(acc[r][3]);
    float* o = gout + (size_t)(i0 + r) * gstride + c0;
    *reinterpret_cast<float4*>(o)     = make_float4(f0.x, f0.y, f1.x, f1.y);
    *reinterpret_cast<float4*>(o + 4) = make_float4(f2.x, f2.y, f3.x, f3.y);
  }
}

// ========================= Kernel 1: parallel precompute ===================
struct Smem1 {
  float qv[Lc][DKc];   // q_norm (swizzled); later vg half
  float k [Lc][DKc];   // k_norm (swizzled); later kg
  float a [Lc][Lc];
  float t [Lc][Lc];
  float p [32][Lc];    // solve off-diagonal scratch
  float part[2][Lc][4];
  float ninv[2][Lc];
  float gcum[Lc]; float gexp[Lc]; float ginv[Lc]; float beta[Lc];
};

__global__ void __launch_bounds__(256, 2) gdn_pre(
    const float* __restrict__ gq, const float* __restrict__ gk,
    const float* __restrict__ gv, const float* __restrict__ gg,
    const float* __restrict__ gb)
{
  extern __shared__ char smem_raw[];
  Smem1& s = *reinterpret_cast<Smem1*>(smem_raw);
  const int tid = threadIdx.x;
  const int n   = blockIdx.x;
  const int bh  = blockIdx.y;
  const size_t rowbase = (size_t)bh * Sc + (size_t)n * Lc;

  const int ldrow = tid >> 2;
  const int ldq   = tid & 3;

  // ---- A: load + norms + gates ----
  const float* qg  = gq + rowbase * DKc + tid * 32;
  const float* kgp = gk + rowbase * DKc + tid * 32;
  float4 bq[8], bk[8];
  float sq = 0.f, sk = 0.f;
  #pragma unroll
  for (int u = 0; u < 8; ++u) {
    float4 x = *reinterpret_cast<const float4*>(qg + u * 4);
    float4 y = *reinterpret_cast<const float4*>(kgp + u * 4);
    bq[u] = x; bk[u] = y;
    sq += x.x * x.x + x.y * x.y + x.z * x.z + x.w * x.w;
    sk += y.x * y.x + y.y * y.y + y.z * y.z + y.w * y.w;
  }
  s.part[0][ldrow][ldq] = sq;
  s.part[1][ldrow][ldq] = sk;
  if (tid < Lc) {
    s.gcum[tid] = gg[(size_t)bh * Sc + n * Lc + tid];
    s.beta[tid] = gb[(size_t)bh * Sc + n * Lc + tid];
  }
  __syncthreads();
  if (tid < 2 * Lc) {
    int w = tid >> 6, r = tid & 63;
    const float* p = s.part[w][r];
    float ssum = (p[0] + p[1]) + (p[2] + p[3]);
    s.ninv[w][r] = 1.f / (sqrtf(ssum) + 1e-6f);
  }
  if (tid == 128) {
    float acc = 0.f;
    for (int i = 0; i < Lc; ++i) { acc += s.gcum[i]; s.gcum[i] = acc; }
  }
  __syncthreads();
  if (tid < Lc) {
    float e = expf(s.gcum[tid]);
    s.gexp[tid] = e;
    s.ginv[tid] = 1.f / e;
  }
  float iq = s.ninv[0][ldrow], ik = s.ninv[1][ldrow];
  {
    const int swr = ((ldrow >> 2) & 7) << 2;
    #pragma unroll
    for (int u = 0; u < 8; ++u) {
      int cc = (ldq * 32 + u * 4) ^ swr;
      float4 x = bq[u];
      x.x *= iq; x.y *= iq; x.z *= iq; x.w *= iq;
      *reinterpret_cast<float4*>(&s.qv[ldrow][cc]) = x;
      float4 y = bk[u];
      y.x *= ik; y.y *= ik; y.z *= ik; y.w *= ik;
      *reinterpret_cast<float4*>(&s.k[ldrow][cc]) = y;
    }
  }
  __syncthreads();

  // ---- epilogue: qhat / kg to gmem; egt ----
  {
    float ge = s.gexp[ldrow];
    float fq = iq * ge, fk = ik * ge;
    float* qo = g_qhat + rowbase * DKc + tid * 32;
    float* ko = g_kg   + rowbase * DKc + tid * 32;
    #pragma unroll
    for (int u = 0; u < 8; ++u) {
      float4 x = bq[u];
      x.x *= fq; x.y *= fq; x.z *= fq; x.w *= fq;
      *reinterpret_cast<float4*>(qo + u * 4) = x;
      float4 y = bk[u];
      y.x *= fk; y.y *= fk; y.z *= fk; y.w *= fk;
      *reinterpret_cast<float4*>(ko + u * 4) = y;
    }
  }
  if (tid == 0) g_egt[bh * NCH + n] = s.gexp[Lc - 1];

  // ---- B: A = gated strict-lower kk^T ; qkg -> gmem ----
  {
    const int ty = tid >> 4, tx = tid & 15;
    const int i0 = ty * 4, j0 = tx * 4;
    const int sA = (ty & 7) << 2, sB = (tx & 7) << 2;
    {
      u64 aA[4][4] = {};
      gemm_pass_4x4(aA, s.k, s.k, i0, j0, sA, sB);
      #pragma unroll
      for (int r = 0; r < 4; ++r) {
        int i = i0 + r;
        float bi = s.beta[i] * s.ginv[i];
        float4 ra;
        ra.x = (j0 + 0 < i) ? bi * foldp(aA[r][0]) * s.gexp[j0 + 0] : 0.f;
        ra.y = (j0 + 1 < i) ? bi * foldp(aA[r][1]) * s.gexp[j0 + 1] : 0.f;
        ra.z = (j0 + 2 < i) ? bi * foldp(aA[r][2]) * s.gexp[j0 + 2] : 0.f;
        ra.w = (j0 + 3 < i) ? bi * foldp(aA[r][3]) * s.gexp[j0 + 3] : 0.f;
        *reinterpret_cast<float4*>(&s.a[i][j0]) = ra;
      }
    }
    {
      u64 aQ[4][4] = {};
      gemm_pass_4x4(aQ, s.qv, s.k, i0, j0, sA, sB);
      #pragma unroll
      for (int r = 0; r < 4; ++r) {
        int i = i0 + r;
        float gi = s.ginv[i];
        float4 rw;
        rw.x = (j0 + 0 <= i) ? foldp(aQ[r][0]) * s.gexp[j0 + 0] * gi : 0.f;
        rw.y = (j0 + 1 <= i) ? foldp(aQ[r][1]) * s.gexp[j0 + 1] * gi : 0.f;
        rw.z = (j0 + 2 <= i) ? foldp(aQ[r][2]) * s.gexp[j0 + 2] * gi : 0.f;
        rw.w = (j0 + 3 <= i) ? foldp(aQ[r][3]) * s.gexp[j0 + 3] * gi : 0.f;
        *reinterpret_cast<float4*>(g_qkg + (rowbase + i) * Lc + j0) = rw;
      }
    }
  }
  __syncthreads();

  // ---- D: solve T = A^-1 diag(beta); overlap kg-scale + vg1 load ----
  if (tid < Lc) {
    float tc[32];
    #pragma unroll
    for (int i = 0; i < 32; ++i) {
      float v0 = (tid == i) ? s.beta[i] : 0.f;
      float v1 = 0.f, v2 = 0.f, v3 = 0.f;
      int j = 0;
      #pragma unroll
      for (; j + 4 <= i; j += 4) {
        v0 -= s.a[i][j + 0] * tc[j + 0];
        v1 -= s.a[i][j + 1] * tc[j + 1];
        v2 -= s.a[i][j + 2] * tc[j + 2];
        v3 -= s.a[i][j + 3] * tc[j + 3];
      }
      #pragma unroll
      for (; j < i; ++j) v0 -= s.a[i][j] * tc[j];
      float val = (v0 + v1) + (v2 + v3);
      tc[i] = val;
      s.t[i][tid] = val;
    }
  } else if (tid < 128) {
    // kg-scale: s.k rows *= gexp (becomes kg). FULL row: 32 float4s.
    int row = tid - 64;
    float ge = s.gexp[row];
    float* rp = &s.k[row][0];
    #pragma unroll
    for (int u = 0; u < 32; ++u) {
      float4 x = *reinterpret_cast<float4*>(rp + u * 4);
      x.x *= ge; x.y *= ge; x.z *= ge; x.w *= ge;
      *reinterpret_cast<float4*>(rp + u * 4) = x;
    }
  } else {
    // vg half1 load: 128 threads, 64 floats each (cols 0..127 of v)
    int v2 = tid - 128;
    int row = v2 >> 1, col0 = (v2 & 1) * 64;
    float ge = s.gexp[row];
    const int swr = ((row >> 2) & 7) << 2;
    const float* vp = gv + (rowbase + row) * DVc + col0;
    #pragma unroll
    for (int u = 0; u < 16; ++u) {
      float4 x = *reinterpret_cast<const float4*>(vp + u * 4);
      x.x *= ge; x.y *= ge; x.z *= ge; x.w *= ge;
      *reinterpret_cast<float4*>(&s.qv[row][(col0 + u * 4) ^ swr]) = x;
    }
  }
  __syncthreads();
  {  // P = A[32:64][0:32] @ T[0:32][:]
    const int rp0 = (tid >> 5) * 4;
    const int cp0 = (tid & 31) * 2;
    float accP[4][2] = {};
    #pragma unroll
    for (int j = 0; j < 32; j += 4) {
      float Bf[4][2];
      #pragma unroll
      for (int jj = 0; jj < 4; ++jj) {
        float2 t2 = *reinterpret_cast<const float2*>(&s.t[j + jj][cp0]);
        Bf[jj][0] = t2.x; Bf[jj][1] = t2.y;
      }
      #pragma unroll
      for (int r = 0; r < 4; ++r) {
        float4 av = *reinterpret_cast<const float4*>(&s.a[32 + rp0 + r][j]);
        accP[r][0] += av.x * Bf[0][0] + av.y * Bf[1][0] + av.z * Bf[2][0] + av.w * Bf[3][0];
        accP[r][1] += av.x * Bf[0][1] + av.y * Bf[1][1] + av.z * Bf[2][1] + av.w * Bf[3][1];
      }
    }
    #pragma unroll
    for (int r = 0; r < 4; ++r) {
      s.p[rp0 + r][cp0]     = accP[r][0];
      s.p[rp0 + r][cp0 + 1] = accP[r][1];
    }
  }
  __syncthreads();
  if (tid < Lc) {
    float tc[32];
    #pragma unroll
    for (int i = 0; i < 32; ++i) {
      int gi = 32 + i;
      float v0 = ((tid == gi) ? s.beta[gi] : 0.f) - s.p[i][tid];
      float v1 = 0.f, v2 = 0.f, v3 = 0.f;
      int j = 0;
      #pragma unroll
      for (; j + 4 <= i; j += 4) {
        v0 -= s.a[gi][32 + j + 0] * tc[j + 0];
        v1 -= s.a[gi][32 + j + 1] * tc[j + 1];
        v2 -= s.a[gi][32 + j + 2] * tc[j + 2];
        v3 -= s.a[gi][32 + j + 3] * tc[j + 3];
      }
      #pragma unroll
      for (; j < i; ++j) v0 -= s.a[gi][32 + j] * tc[j];
      float val = (v0 + v1) + (v2 + v3);
      tc[i] = val;
      s.t[gi][tid] = val;
    }
  }
  __syncthreads();

  // ---- E: W = T@kg -> gmem; U0 half1 = T@vg1 -> gmem ----
  {
    const int i0 = (tid >> 4) * 4;
    const int c0 = (tid & 15) * 8;
    tri_mm(s.t, s.k,  g_W  + rowbase * DKc, DKc, i0, c0);
    tri_mm(s.t, s.qv, g_U0 + rowbase * DVc, DVc, i0, c0);
  }
  __syncthreads();
  {  // vg half2 load (all 256 threads, 32 floats each)
    int row = tid >> 2, col0 = (tid & 3) * 32;
    float ge = s.gexp[row];
    const int swr = ((row >> 2) & 7) << 2;
    const float* vp = gv + (rowbase + row) * DVc + 128 + col0;
    #pragma unroll
    for (int u = 0; u < 8; ++u) {
      float4 x = *reinterpret_cast<const float4*>(vp + u * 4);
      x.x *= ge; x.y *= ge; x.z *= ge; x.w *= ge;
      *reinterpret_cast<float4*>(&s.qv[row][(col0 + u * 4) ^ swr]) = x;
    }
  }
  __syncthreads();
  {
    const int i0 = (tid >> 4) * 4;
    const int c0 = (tid & 15) * 8;
    tri_mm(s.t, s.qv, g_U0 + rowbase * DVc + 128, DVc, i0, c0);
  }
}

// ========================= Kernel 2: sequential scan =======================
struct Smem2 {
  float St [DVB][DKc];   // state slice, transposed, swizzled
  float qh [Lc][DKc];    // qhat (swizzled)
  float W  [Lc][DKc];    // W (swizzled)
  float kg [Lc][DKc];    // kg (swizzled)
  float u0 [Lc][DVB];    // U0 slice -> becomes C in place
  float qkg[Lc][Lc];
  float oi [Lc][DVB];    // qhat @ S
};

__global__ void __launch_bounds__(512, 1) gdn_scan(
    float* __restrict__ out, long long out_elems)
{
  extern __shared__ char smem_raw[];
  Smem2& s = *reinterpret_cast<Smem2*>(smem_raw);
  const int tid = threadIdx.x;
  const int vb  = blockIdx.x;
  const int bh  = blockIdx.y;

  for (int i = tid; i < DKc * DVB; i += 512) (&s.St[0][0])[i] = 0.f;
  __syncthreads();

  const int half = tid >> 8;
  const int htid = tid & 255;
  const int hy   = htid >> 4;
  const int hx   = htid & 15;

  for (int n = 0; n < NCH; ++n) {
    const size_t rb = (size_t)bh * Sc + (size_t)n * Lc;
    // ---- load tiles ----
    {
      int row = tid >> 3, c16 = (tid & 7) * 16;
      const int swr = ((row >> 2) & 7) << 2;
      const float* pq = g_qhat + (rb + row) * DKc + c16;
      const float* pw = g_W    + (rb + row) * DKc + c16;
      const float* pk = g_kg   + (rb + row) * DKc + c16;
      #pragma unroll
      for (int u = 0; u < 4; ++u) {
        int cc = (c16 + u * 4) ^ swr;
        LD4(&s.qh[row][cc], pq + u * 4);
        LD4(&s.W[row][cc],  pw + u * 4);
        LD4(&s.kg[row][cc], pk + u * 4);
      }
      int c8 = (tid & 7) * 8;
      const float* pu = g_U0 + (rb + row) * DVc + vb * DVB + c8;
      LD4(&s.u0[row][c8],     pu);
      LD4(&s.u0[row][c8 + 4], pu + 4);
      const float* pg = g_qkg + (rb + row) * Lc + c8;
      LD4(&s.qkg[row][c8],     pg);
      LD4(&s.qkg[row][c8 + 4], pg + 4);
    }
    const float egt = g_egt[bh * NCH + n];
    __syncthreads();

    // ---- P1: C = U0 - W@S (half0)  ∥  oi = qhat@S (half1) ----
    {
      const int i0 = hy * 4, c0 = hx * 4;
      const int sA = (hy & 7) << 2, sB = (hx & 7) << 2;
      if (half == 0) {
        u64 acc[4][4] = {};
        gemm_pass_4x4(acc, s.W, s.St, i0, c0, sA, sB);
        #pragma unroll
        for (int r = 0; r < 4; ++r) {
          float4 uv = *reinterpret_cast<float4*>(&s.u0[i0 + r][c0]);
          uv.x -= foldp(acc[r][0]);
          uv.y -= foldp(acc[r][1]);
          uv.z -= foldp(acc[r][2]);
          uv.w -= foldp(acc[r][3]);
          *reinterpret_cast<float4*>(&s.u0[i0 + r][c0]) = uv;
        }
      } else {
        u64 acc[4][4] = {};
        gemm_pass_4x4(acc, s.qh, s.St, i0, c0, sA, sB);
        #pragma unroll
        for (int r = 0; r < 4; ++r) {
          *reinterpret_cast<float4*>(&s.oi[i0 + r][c0]) =
              make_float4(foldp(acc[r][0]), foldp(acc[r][1]),
                          foldp(acc[r][2]), foldp(acc[r][3]));
        }
      }
    }
    __syncthreads();   // C (in s.u0) and oi complete

    // ---- P2: O store (half1)  ∥  state update (half0) ----
    if (half == 1) {
      const int i0 = hy * 4, c0 = hx * 4;
      u64 aO[4][2] = {};
      #pragma unroll 2
      for (int j = 0; j <= i0; j += 4) {
        u64 Bv[4][2];
        #pragma unroll
        for (int jj = 0; jj < 4; ++jj) ldBv(Bv[jj], &s.u0[j + jj][c0]);
        float Af[4][4];
        #pragma unroll
        for (int r = 0; r < 4; ++r) LD4(&Af[r][0], &s.qkg[i0 + r][j]);
        mm4x4p(aO, Af, Bv);
      }
      const size_t obase = rb * DVc + (size_t)vb * DVB;
      #pragma unroll
      for (int r = 0; r < 4; ++r) {
        int i = i0 + r;
        float2 o0 = upk(aO[r][0]), o1 = upk(aO[r][1]);
        float4 oi4 = *reinterpret_cast<const float4*>(&s.oi[i][c0]);
        float4 o;
        o.x = kScale * (oi4.x + o0.x);
        o.y = kScale * (oi4.y + o0.y);
        o.z = kScale * (oi4.z + o1.x);
        o.w = kScale * (oi4.w + o1.y);
        *reinterpret_cast<float4*>(&out[obase + (size_t)i * DVc + c0]) = o;
      }
    } else {
      // St[c][d] = egt*St[c][d] + sum_i C[i][c] * kg[i][d]
      const int c0 = (tid & 15) * 4;
      const int d0 = (tid >> 4) * 8;
      const int sc = ((tid & 15) & 7) << 2;
      const u64 egt2 = pk2(egt);
      u64 acc[4][4] = {};
      #pragma unroll 2
      for (int i = 0; i < Lc; ++i) {
        const int si = ((i >> 2) & 7) << 2;
        u64 kp[4];
        ld2p(kp,     &s.kg[i][d0 ^ si]);
        ld2p(kp + 2, &s.kg[i][(d0 + 4) ^ si]);
        float4 cv = *reinterpret_cast<const float4*>(&s.u0[i][c0]);
        u64 gc0 = pk2(cv.x), gc1 = pk2(cv.y);
        u64 gc2 = pk2(cv.z), gc3 = pk2(cv.w);
        #pragma unroll
        for (int dp = 0; dp < 4; ++dp) {
          acc[0][dp] = ffma2(gc0, kp[dp], acc[0][dp]);
          acc[1][dp] = ffma2(gc1, kp[dp], acc[1][dp]);
          acc[2][dp] = ffma2(gc2, kp[dp], acc[2][dp]);
          acc[3][dp] = ffma2(gc3, kp[dp], acc[3][dp]);
        }
      }
      #pragma unroll
      for (int cc = 0; cc < 4; ++cc) {
        float* row = &s.St[c0 + cc][0];
        u64* p0 = reinterpret_cast<u64*>(row + (d0 ^ sc));
        u64* p1 = reinterpret_cast<u64*>(row + ((d0 + 4) ^ sc));
        p0[0] = ffma2(p0[0], egt2, acc[cc][0]);
        p0[1] = ffma2(p0[1], egt2, acc[cc][1]);
        p1[0] = ffma2(p1[0], egt2, acc[cc][2]);
        p1[1] = ffma2(p1[1], egt2, acc[cc][3]);
      }
    }
    __syncthreads();
  }

  if (out_elems >= OUT_ELEMS + STATE_ELEMS) {
    float* st = out + OUT_ELEMS + (size_t)bh * DKc * DVc + (size_t)vb * DVB;
    for (int f = tid; f < DKc * DVB; f += 512) {
      int d = f >> 6;
      int c = f & 63;
      st[(size_t)d * DVc + c] = s.St[c][SWZ(c, d)];
    }
  }
}

}  // namespace

extern "C" void kernel_launch(void* const* d_in, const int* in_sizes, int n_in,
                              void* d_out, int out_size) {
  (void)in_sizes; (void)n_in;
  const float* q  = (const float*)d_in[0];
  const float* k  = (const float*)d_in[1];
  const float* v  = (const float*)d_in[2];
  const float* g  = (const float*)d_in[3];
  const float* be = (const float*)d_in[4];

  cudaFuncSetAttribute(gdn_pre, cudaFuncAttributeMaxDynamicSharedMemorySize,
                       (int)sizeof(Smem1));
  cudaFuncSetAttribute(gdn_scan, cudaFuncAttributeMaxDynamicSharedMemorySize,
                       (int)sizeof(Smem2));

  gdn_pre<<<dim3(NCH, BHc), 256, sizeof(Smem1)>>>(q, k, v, g, be);
  gdn_scan<<<dim3(NBv, BHc), 512, sizeof(Smem2)>>>((float*)d_out,
                                                   (long long)out_size);
}